// round 9
// baseline (speedup 1.0000x reference)
#include <cuda_runtime.h>
#include <cuda_fp16.h>
#include <math.h>

#define NNODES   100000
#define NEDGES   1600000
#define F_IN     128
#define F_HID    64
#define N_GRAPHS 128
#define BUCKET   64   // max in-degree capacity (Poisson(16): P(>=64) ~ 1e-24)

// scratch
__device__ int    g_count[NNODES];                  // in-degree (no self loop)
__device__ int    g_bucket[(size_t)NNODES * BUCKET];// neighbor lists
__device__ float  g_dis[NNODES];                    // (deg+1)^{-1/2}
__device__ __align__(16) __half g_bufAh[(size_t)NNODES * F_HID]; // dis-prescaled feats
__device__ __align__(16) __half g_bufBh[(size_t)NNODES * F_HID]; // layer-1 activations
__device__ float  g_pool[N_GRAPHS * F_HID];
__device__ float  g_cnt[N_GRAPHS];

__device__ __forceinline__ void red_add_v4(float* addr, float4 v) {
    asm volatile("red.global.add.v4.f32 [%0], {%1, %2, %3, %4};"
                 :: "l"(addr), "f"(v.x), "f"(v.y), "f"(v.z), "f"(v.w)
                 : "memory");
}

__device__ __forceinline__ unsigned smem_u32(const void* p) {
    return (unsigned)__cvta_generic_to_shared(p);
}

// ---------------------------------------------------------------------------
__global__ void k_zero(int n) {
    int i = blockIdx.x * blockDim.x + threadIdx.x;
    if (i < n) g_count[i] = 0;
    if (i < N_GRAPHS * F_HID) g_pool[i] = 0.0f;
    if (i < N_GRAPHS) g_cnt[i] = 0.0f;
}

// single-pass bucket fill (histogram + placement in one atomic)
__global__ void k_fill(const int* __restrict__ src,
                       const int* __restrict__ dst, int nE4) {
    int t = blockIdx.x * blockDim.x + threadIdx.x;
    if (t >= nE4) return;
    int4 s4 = ((const int4*)src)[t];
    int4 d4 = ((const int4*)dst)[t];
    int p0 = atomicAdd(&g_count[d4.x], 1);
    int p1 = atomicAdd(&g_count[d4.y], 1);
    int p2 = atomicAdd(&g_count[d4.z], 1);
    int p3 = atomicAdd(&g_count[d4.w], 1);
    if (p0 < BUCKET) g_bucket[(size_t)d4.x * BUCKET + p0] = s4.x;
    if (p1 < BUCKET) g_bucket[(size_t)d4.y * BUCKET + p1] = s4.y;
    if (p2 < BUCKET) g_bucket[(size_t)d4.z * BUCKET + p2] = s4.z;
    if (p3 < BUCKET) g_bucket[(size_t)d4.w * BUCKET + p3] = s4.w;
}

__global__ void k_prep(const int* __restrict__ batch, int n) {
    int i = blockIdx.x * blockDim.x + threadIdx.x;
    if (i >= n) return;
    g_dis[i] = rsqrtf((float)g_count[i] + 1.0f);
    atomicAdd(&g_cnt[batch[i]], 1.0f);
}

// ---------------------------------------------------------------------------
// Tensor-core GEMM with cp.async double-buffered X staging.
//   bufAh[n,64] = fp16( dis * (X[n,K] @ W[K,64]) )
// 256 threads = 8 warps; tile 128 nodes. Warp w: nodes w*16..w*16+15, all 64 cols.
// GEMM1: stages raw fp32 (KC=16, 96B row stride), converts at fragment load.
// GEMM2: stages fp16 (KC=32, 80B row stride).
// ---------------------------------------------------------------------------
template <int K, int KC, bool FROM_HALF>
__global__ void __launch_bounds__(256) k_gemm_mma(const float* __restrict__ Xf,
                                                  const float* __restrict__ W,
                                                  int n) {
    constexpr int WP = K + 8;                    // Ws stride (halves)
    constexpr int XROWB = FROM_HALF ? 80 : 96;   // staged row stride in bytes
    __shared__ __half Ws[64 * WP];
    __shared__ __align__(16) unsigned char Xraw[2][128 * XROWB];

    int tid = threadIdx.x;

    // W [K][64] fp32 -> Ws[nCol][k] fp16 (one-time transpose)
    for (int i = tid; i < K * 64; i += 256) {
        int k = i >> 6, nn = i & 63;
        Ws[nn * WP + k] = __float2half(W[i]);
    }

    int nodeBase = blockIdx.x * 128;
    int warp = tid >> 5, lane = tid & 31;
    int gid = lane >> 2, tg = lane & 3;

    float c[8][4];
#pragma unroll
    for (int i = 0; i < 8; i++)
#pragma unroll
        for (int j = 0; j < 4; j++) c[i][j] = 0.0f;

    // async stage of one KC-chunk (64B per row) into buffer b
    auto stage = [&](int k0, int b) {
#pragma unroll
        for (int o = tid; o < 512; o += 256) {
            int r = o >> 2, seg = o & 3;
            int node = nodeBase + r;
            unsigned dst = smem_u32(&Xraw[b][r * XROWB + seg * 16]);
            const void* src;
            if (FROM_HALF)
                src = g_bufBh + (size_t)node * 64 + k0 + seg * 8;
            else
                src = Xf + (size_t)node * K + k0 + seg * 4;
            int sz = (node < n) ? 16 : 0;
            asm volatile("cp.async.ca.shared.global [%0], [%1], 16, %2;\n"
                         :: "r"(dst), "l"(src), "r"(sz));
        }
        asm volatile("cp.async.commit_group;\n");
    };

    stage(0, 0);
    int buf = 0;

    for (int k0 = 0; k0 < K; k0 += KC) {
        asm volatile("cp.async.wait_group 0;\n");
        __syncthreads();
        if (k0 + KC < K) stage(k0 + KC, buf ^ 1);

        if (!FROM_HALF) {
            // KC=16: one k-tile; fp32 rows, stride 24 words; convert to half here
            const float* xb = (const float*)Xraw[buf];
            const float* p0 = xb + (warp * 16 + gid) * 24 + tg * 2;
            float2 f0 = *(const float2*)p0;
            float2 f1 = *(const float2*)(p0 + 8 * 24);
            float2 f2 = *(const float2*)(p0 + 8);
            float2 f3 = *(const float2*)(p0 + 8 * 24 + 8);
            __half2 h0 = __floats2half2_rn(f0.x, f0.y);
            __half2 h1 = __floats2half2_rn(f1.x, f1.y);
            __half2 h2 = __floats2half2_rn(f2.x, f2.y);
            __half2 h3 = __floats2half2_rn(f3.x, f3.y);
            unsigned a0 = *(unsigned*)&h0, a1 = *(unsigned*)&h1;
            unsigned a2 = *(unsigned*)&h2, a3 = *(unsigned*)&h3;
#pragma unroll
            for (int nt = 0; nt < 8; nt++) {
                const __half* br = &Ws[(nt * 8 + gid) * WP + k0 + tg * 2];
                unsigned b0 = *(const unsigned*)br;
                unsigned b1 = *(const unsigned*)(br + 8);
                asm volatile(
                    "mma.sync.aligned.m16n8k16.row.col.f32.f16.f16.f32 "
                    "{%0,%1,%2,%3}, {%4,%5,%6,%7}, {%8,%9}, {%0,%1,%2,%3};"
                    : "+f"(c[nt][0]), "+f"(c[nt][1]),
                      "+f"(c[nt][2]), "+f"(c[nt][3])
                    : "r"(a0), "r"(a1), "r"(a2), "r"(a3), "r"(b0), "r"(b1));
            }
        } else {
            // KC=32: two k-tiles; fp16 rows, stride 40 halves
            const __half* xb = (const __half*)Xraw[buf];
#pragma unroll
            for (int kt = 0; kt < 2; kt++) {
                int kk = kt * 16;
                const __half* p0 = xb + (warp * 16 + gid) * 40 + kk + tg * 2;
                unsigned a0 = *(const unsigned*)p0;
                unsigned a1 = *(const unsigned*)(p0 + 8 * 40);
                unsigned a2 = *(const unsigned*)(p0 + 8);
                unsigned a3 = *(const unsigned*)(p0 + 8 * 40 + 8);
#pragma unroll
                for (int nt = 0; nt < 8; nt++) {
                    const __half* br = &Ws[(nt * 8 + gid) * WP + k0 + kk + tg * 2];
                    unsigned b0 = *(const unsigned*)br;
                    unsigned b1 = *(const unsigned*)(br + 8);
                    asm volatile(
                        "mma.sync.aligned.m16n8k16.row.col.f32.f16.f16.f32 "
                        "{%0,%1,%2,%3}, {%4,%5,%6,%7}, {%8,%9}, {%0,%1,%2,%3};"
                        : "+f"(c[nt][0]), "+f"(c[nt][1]),
                          "+f"(c[nt][2]), "+f"(c[nt][3])
                        : "r"(a0), "r"(a1), "r"(a2), "r"(a3), "r"(b0), "r"(b1));
                }
            }
        }
        buf ^= 1;
        __syncthreads();
    }

    // epilogue: scale by dis, store fp16 (dis-prescaled for gather)
    int node0 = nodeBase + warp * 16 + gid;
    int node1 = node0 + 8;
    if (node0 < n) {
        float d = g_dis[node0];
#pragma unroll
        for (int nt = 0; nt < 8; nt++) {
            __half2 h = __floats2half2_rn(c[nt][0] * d, c[nt][1] * d);
            *(__half2*)&g_bufAh[(size_t)node0 * 64 + nt * 8 + tg * 2] = h;
        }
    }
    if (node1 < n) {
        float d = g_dis[node1];
#pragma unroll
        for (int nt = 0; nt < 8; nt++) {
            __half2 h = __floats2half2_rn(c[nt][2] * d, c[nt][3] * d);
            *(__half2*)&g_bufAh[(size_t)node1 * 64 + nt * 8 + tg * 2] = h;
        }
    }
}

// ---------------------------------------------------------------------------
// gather core on dis-prescaled fp16 features, 8 lanes/node x 16B loads:
//   out_i = dis_i * ( scaled[i] + sum_s scaled[s] )
// ---------------------------------------------------------------------------
__device__ __forceinline__ void acc8(float* acc, uint4 u) {
    __half2* h = (__half2*)&u;
#pragma unroll
    for (int t = 0; t < 4; t++) {
        float2 f = __half22float2(h[t]);
        acc[2 * t] += f.x;
        acc[2 * t + 1] += f.y;
    }
}

__device__ __forceinline__ void gather_core(int i, int q, float* acc) {
    const uint4* A = (const uint4*)g_bufAh;   // row = 8 x uint4
    uint4 self = A[(size_t)i * 8 + q];
    {
        __half2* h = (__half2*)&self;
#pragma unroll
        for (int t = 0; t < 4; t++) {
            float2 f = __half22float2(h[t]);
            acc[2 * t] = f.x;
            acc[2 * t + 1] = f.y;
        }
    }
    int cnt = min(g_count[i], BUCKET);
    const int* nb = g_bucket + (size_t)i * BUCKET;
    int j = 0;
    for (; j + 4 <= cnt; j += 4) {
        int s0 = nb[j], s1 = nb[j + 1], s2 = nb[j + 2], s3 = nb[j + 3];
        uint4 u0 = A[(size_t)s0 * 8 + q];
        uint4 u1 = A[(size_t)s1 * 8 + q];
        uint4 u2 = A[(size_t)s2 * 8 + q];
        uint4 u3 = A[(size_t)s3 * 8 + q];
        acc8(acc, u0); acc8(acc, u1); acc8(acc, u2); acc8(acc, u3);
    }
    for (; j < cnt; j++)
        acc8(acc, A[(size_t)nb[j] * 8 + q]);
    float di = g_dis[i];
#pragma unroll
    for (int t = 0; t < 8; t++) acc[t] *= di;
}

// gather1: bufBh[i] = fp16(relu(gather + b1))
__global__ void k_gather1(const float* __restrict__ b1, int n) {
    int idx = blockIdx.x * blockDim.x + threadIdx.x;
    int i = idx >> 3, q = idx & 7;
    if (i >= n) return;
    float acc[8];
    gather_core(i, q, acc);
    const float* bb = b1 + q * 8;
    uint4 st;
    __half2* h = (__half2*)&st;
#pragma unroll
    for (int t = 0; t < 4; t++) {
        float x0 = fmaxf(acc[2 * t] + bb[2 * t], 0.0f);
        float x1 = fmaxf(acc[2 * t + 1] + bb[2 * t + 1], 0.0f);
        h[t] = __floats2half2_rn(x0, x1);
    }
    ((uint4*)(g_bufBh + (size_t)i * 64))[q] = st;
}

// gather2 fused with pooling: pool[batch[i]] += relu(gather + b2)
__global__ void k_gather2_pool(const int* __restrict__ batch,
                               const float* __restrict__ b2, int n) {
    int idx = blockIdx.x * blockDim.x + threadIdx.x;
    int i = idx >> 3, q = idx & 7;
    if (i >= n) return;
    float acc[8];
    gather_core(i, q, acc);
    const float* bb = b2 + q * 8;
#pragma unroll
    for (int t = 0; t < 8; t++) acc[t] = fmaxf(acc[t] + bb[t], 0.0f);
    int g = batch[i];
    red_add_v4(g_pool + g * 64 + q * 8,
               make_float4(acc[0], acc[1], acc[2], acc[3]));
    red_add_v4(g_pool + g * 64 + q * 8 + 4,
               make_float4(acc[4], acc[5], acc[6], acc[7]));
}

__global__ void k_final(const float* __restrict__ Wf, const float* __restrict__ bf,
                        float* __restrict__ out) {
    int t = threadIdx.x;
    if (t >= N_GRAPHS * 2) return;
    int g = t >> 1, c = t & 1;
    float acc = 0.0f;
#pragma unroll
    for (int j = 0; j < F_HID; j++)
        acc = fmaf(g_pool[g * 64 + j], Wf[j * 2 + c], acc);
    float cnt = fmaxf(g_cnt[g], 1.0f);
    out[g * 2 + c] = acc / cnt + bf[c];
}

// ---------------------------------------------------------------------------
extern "C" void kernel_launch(void* const* d_in, const int* in_sizes, int n_in,
                              void* d_out, int out_size) {
    const float* x    = (const float*)d_in[0];
    const int*   ei   = (const int*)d_in[1];  // [2, E] int32
    const int*   batch= (const int*)d_in[2];
    const float* W1   = (const float*)d_in[3];
    const float* b1   = (const float*)d_in[4];
    const float* W2   = (const float*)d_in[5];
    const float* b2   = (const float*)d_in[6];
    const float* Wf   = (const float*)d_in[7];
    const float* bf   = (const float*)d_in[8];
    float* out = (float*)d_out;

    int n  = in_sizes[0] / F_IN;   // 100000
    int nE = in_sizes[1] / 2;      // 1600000 (multiple of 4)
    const int* src = ei;
    const int* dst = ei + nE;

    const int T = 256;
    int gN   = (n + T - 1) / T;
    int nE4  = nE / 4;
    int gE4  = (nE4 + T - 1) / T;
    int gN8  = (int)(((size_t)n * 8 + T - 1) / T);
    int gGemm = (n + 127) / 128;

    // graph structure (bucket CSR, single pass) + normalization
    k_zero<<<gN, T>>>(n);
    k_fill<<<gE4, T>>>(src, dst, nE4);
    k_prep<<<gN, T>>>(batch, n);

    // layer 1 (tensor-core GEMM, fp32 X, cp.async pipelined)
    k_gemm_mma<F_IN, 16, false><<<gGemm, T>>>(x, W1, n);
    k_gather1<<<gN8, T>>>(b1, n);

    // layer 2 (tensor-core GEMM, fp16 input from gather1)
    k_gemm_mma<F_HID, 32, true><<<gGemm, T>>>(nullptr, W2, n);
    k_gather2_pool<<<gN8, T>>>(batch, b2, n);

    // classifier
    k_final<<<1, T>>>(Wf, bf, out);
}

// round 10
// speedup vs baseline: 1.0740x; 1.0740x over previous
#include <cuda_runtime.h>
#include <cuda_fp16.h>
#include <math.h>

#define NNODES   100000
#define NEDGES   1600000
#define F_IN     128
#define F_HID    64
#define N_GRAPHS 128
#define BUCKET   64   // max in-degree capacity (Poisson(16): P(>=64) ~ 1e-24)

// scratch
__device__ int    g_count[NNODES];                  // in-degree (no self loop)
__device__ int    g_bucket[(size_t)NNODES * BUCKET];// neighbor lists
__device__ float  g_dis[NNODES];                    // (deg+1)^{-1/2}
__device__ __align__(16) __half g_bufAh[(size_t)NNODES * F_HID]; // dis-prescaled feats
__device__ __align__(16) __half g_bufBh[(size_t)NNODES * F_HID]; // layer-1 activations
__device__ float  g_pool[N_GRAPHS * F_HID];
__device__ float  g_cnt[N_GRAPHS];

__device__ __forceinline__ void red_add_v4(float* addr, float4 v) {
    asm volatile("red.global.add.v4.f32 [%0], {%1, %2, %3, %4};"
                 :: "l"(addr), "f"(v.x), "f"(v.y), "f"(v.z), "f"(v.w)
                 : "memory");
}

__device__ __forceinline__ unsigned smem_u32(const void* p) {
    return (unsigned)__cvta_generic_to_shared(p);
}

// ---------------------------------------------------------------------------
__global__ void k_zero(int n) {
    int i = blockIdx.x * blockDim.x + threadIdx.x;
    if (i < n) g_count[i] = 0;
    if (i < N_GRAPHS * F_HID) g_pool[i] = 0.0f;
    if (i < N_GRAPHS) g_cnt[i] = 0.0f;
}

// single-pass bucket fill (histogram + placement in one atomic)
__global__ void k_fill(const int* __restrict__ src,
                       const int* __restrict__ dst, int nE4) {
    int t = blockIdx.x * blockDim.x + threadIdx.x;
    if (t >= nE4) return;
    int4 s4 = ((const int4*)src)[t];
    int4 d4 = ((const int4*)dst)[t];
    int p0 = atomicAdd(&g_count[d4.x], 1);
    int p1 = atomicAdd(&g_count[d4.y], 1);
    int p2 = atomicAdd(&g_count[d4.z], 1);
    int p3 = atomicAdd(&g_count[d4.w], 1);
    if (p0 < BUCKET) g_bucket[(size_t)d4.x * BUCKET + p0] = s4.x;
    if (p1 < BUCKET) g_bucket[(size_t)d4.y * BUCKET + p1] = s4.y;
    if (p2 < BUCKET) g_bucket[(size_t)d4.z * BUCKET + p2] = s4.z;
    if (p3 < BUCKET) g_bucket[(size_t)d4.w * BUCKET + p3] = s4.w;
}

__global__ void k_prep(const int* __restrict__ batch, int n) {
    int i = blockIdx.x * blockDim.x + threadIdx.x;
    if (i >= n) return;
    g_dis[i] = rsqrtf((float)g_count[i] + 1.0f);
    atomicAdd(&g_cnt[batch[i]], 1.0f);
}

// ---------------------------------------------------------------------------
// Tensor-core GEMM with multi-stage cp.async X staging.
//   bufAh[n,64] = fp16( dis * (X[n,K] @ W[K,64]) )
// 256 threads = 8 warps; tile 128 nodes. Warp w: nodes w*16..w*16+15, all 64 cols.
// GEMM1 (fp32 X): KC=16, 4 stages (deep prefetch to cover DRAM latency).
// GEMM2 (fp16 X): KC=32, 2 stages (input is L2-resident).
// ---------------------------------------------------------------------------
template <int K, int KC, int STAGES, bool FROM_HALF>
__global__ void __launch_bounds__(256) k_gemm_mma(const float* __restrict__ Xf,
                                                  const float* __restrict__ W,
                                                  int n) {
    constexpr int WP = K + 8;                    // Ws stride (halves)
    constexpr int XROWB = FROM_HALF ? 80 : 96;   // staged row stride (bytes)
    __shared__ __half Ws[64 * WP];
    __shared__ __align__(16) unsigned char Xraw[STAGES][128 * XROWB];

    int tid = threadIdx.x;

    // W [K][64] fp32 -> Ws[nCol][k] fp16 (one-time transpose)
    for (int i = tid; i < K * 64; i += 256) {
        int k = i >> 6, nn = i & 63;
        Ws[nn * WP + k] = __float2half(W[i]);
    }

    int nodeBase = blockIdx.x * 128;
    int warp = tid >> 5, lane = tid & 31;
    int gid = lane >> 2, tg = lane & 3;

    float c[8][4];
#pragma unroll
    for (int i = 0; i < 8; i++)
#pragma unroll
        for (int j = 0; j < 4; j++) c[i][j] = 0.0f;

    // async stage of one KC-chunk (64B per row) into buffer b
    auto stage = [&](int k0, int b) {
#pragma unroll
        for (int o = tid; o < 512; o += 256) {
            int r = o >> 2, seg = o & 3;
            int node = nodeBase + r;
            unsigned dst = smem_u32(&Xraw[b][r * XROWB + seg * 16]);
            const void* src;
            if (FROM_HALF)
                src = g_bufBh + (size_t)node * 64 + k0 + seg * 8;
            else
                src = Xf + (size_t)node * K + k0 + seg * 4;
            int sz = (node < n) ? 16 : 0;   // OOB rows: zero-fill
            asm volatile("cp.async.ca.shared.global [%0], [%1], 16, %2;\n"
                         :: "r"(dst), "l"(src), "r"(sz));
        }
        asm volatile("cp.async.commit_group;\n");
    };

    // prologue: stage first STAGES-1 chunks
#pragma unroll
    for (int s = 0; s < STAGES - 1; s++)
        if (s * KC < K) stage(s * KC, s);

    int ci = 0;  // chunk index
    for (int k0 = 0; k0 < K; k0 += KC, ci++) {
        asm volatile("cp.async.wait_group %0;\n" :: "n"(STAGES - 2));
        __syncthreads();
        if (k0 + (STAGES - 1) * KC < K)
            stage(k0 + (STAGES - 1) * KC, (ci + STAGES - 1) % STAGES);

        int buf = ci % STAGES;
        if (!FROM_HALF) {
            // KC=16: one k-tile; fp32 rows, stride 24 words; convert to half here
            const float* xb = (const float*)Xraw[buf];
            const float* p0 = xb + (warp * 16 + gid) * 24 + tg * 2;
            float2 f0 = *(const float2*)p0;
            float2 f1 = *(const float2*)(p0 + 8 * 24);
            float2 f2 = *(const float2*)(p0 + 8);
            float2 f3 = *(const float2*)(p0 + 8 * 24 + 8);
            __half2 h0 = __floats2half2_rn(f0.x, f0.y);
            __half2 h1 = __floats2half2_rn(f1.x, f1.y);
            __half2 h2 = __floats2half2_rn(f2.x, f2.y);
            __half2 h3 = __floats2half2_rn(f3.x, f3.y);
            unsigned a0 = *(unsigned*)&h0, a1 = *(unsigned*)&h1;
            unsigned a2 = *(unsigned*)&h2, a3 = *(unsigned*)&h3;
#pragma unroll
            for (int nt = 0; nt < 8; nt++) {
                const __half* br = &Ws[(nt * 8 + gid) * WP + k0 + tg * 2];
                unsigned b0 = *(const unsigned*)br;
                unsigned b1 = *(const unsigned*)(br + 8);
                asm volatile(
                    "mma.sync.aligned.m16n8k16.row.col.f32.f16.f16.f32 "
                    "{%0,%1,%2,%3}, {%4,%5,%6,%7}, {%8,%9}, {%0,%1,%2,%3};"
                    : "+f"(c[nt][0]), "+f"(c[nt][1]),
                      "+f"(c[nt][2]), "+f"(c[nt][3])
                    : "r"(a0), "r"(a1), "r"(a2), "r"(a3), "r"(b0), "r"(b1));
            }
        } else {
            // KC=32: two k-tiles; fp16 rows, stride 40 halves
            const __half* xb = (const __half*)Xraw[buf];
#pragma unroll
            for (int kt = 0; kt < 2; kt++) {
                int kk = kt * 16;
                const __half* p0 = xb + (warp * 16 + gid) * 40 + kk + tg * 2;
                unsigned a0 = *(const unsigned*)p0;
                unsigned a1 = *(const unsigned*)(p0 + 8 * 40);
                unsigned a2 = *(const unsigned*)(p0 + 8);
                unsigned a3 = *(const unsigned*)(p0 + 8 * 40 + 8);
#pragma unroll
                for (int nt = 0; nt < 8; nt++) {
                    const __half* br = &Ws[(nt * 8 + gid) * WP + k0 + kk + tg * 2];
                    unsigned b0 = *(const unsigned*)br;
                    unsigned b1 = *(const unsigned*)(br + 8);
                    asm volatile(
                        "mma.sync.aligned.m16n8k16.row.col.f32.f16.f16.f32 "
                        "{%0,%1,%2,%3}, {%4,%5,%6,%7}, {%8,%9}, {%0,%1,%2,%3};"
                        : "+f"(c[nt][0]), "+f"(c[nt][1]),
                          "+f"(c[nt][2]), "+f"(c[nt][3])
                        : "r"(a0), "r"(a1), "r"(a2), "r"(a3), "r"(b0), "r"(b1));
                }
            }
        }
    }

    // epilogue: scale by dis, store fp16 (dis-prescaled for gather)
    int node0 = nodeBase + warp * 16 + gid;
    int node1 = node0 + 8;
    if (node0 < n) {
        float d = g_dis[node0];
#pragma unroll
        for (int nt = 0; nt < 8; nt++) {
            __half2 h = __floats2half2_rn(c[nt][0] * d, c[nt][1] * d);
            *(__half2*)&g_bufAh[(size_t)node0 * 64 + nt * 8 + tg * 2] = h;
        }
    }
    if (node1 < n) {
        float d = g_dis[node1];
#pragma unroll
        for (int nt = 0; nt < 8; nt++) {
            __half2 h = __floats2half2_rn(c[nt][2] * d, c[nt][3] * d);
            *(__half2*)&g_bufAh[(size_t)node1 * 64 + nt * 8 + tg * 2] = h;
        }
    }
}

// ---------------------------------------------------------------------------
// gather core on dis-prescaled fp16 features (R8 shape: 16 lanes/node x 8B):
//   out_i = dis_i * ( scaled[i] + sum_s scaled[s] )
// ---------------------------------------------------------------------------
__device__ __forceinline__ float4 cvt4(uint2 u) {
    float2 lo = __half22float2(*(__half2*)&u.x);
    float2 hi = __half22float2(*(__half2*)&u.y);
    return make_float4(lo.x, lo.y, hi.x, hi.y);
}

__device__ __forceinline__ float4 gather_node(int i, int q) {
    const uint2* A = (const uint2*)g_bufAh;   // row = 16 x 8B
    float4 acc = cvt4(A[(size_t)i * 16 + q]); // self term (already dis_i-scaled)
    int cnt = min(g_count[i], BUCKET);
    const int* nb = g_bucket + (size_t)i * BUCKET;
    int j = 0;
    for (; j + 4 <= cnt; j += 4) {
        int s0 = nb[j], s1 = nb[j + 1], s2 = nb[j + 2], s3 = nb[j + 3];
        uint2 u0 = A[(size_t)s0 * 16 + q];
        uint2 u1 = A[(size_t)s1 * 16 + q];
        uint2 u2 = A[(size_t)s2 * 16 + q];
        uint2 u3 = A[(size_t)s3 * 16 + q];
        float4 v0 = cvt4(u0), v1 = cvt4(u1), v2 = cvt4(u2), v3 = cvt4(u3);
        acc.x += v0.x + v1.x + v2.x + v3.x;
        acc.y += v0.y + v1.y + v2.y + v3.y;
        acc.z += v0.z + v1.z + v2.z + v3.z;
        acc.w += v0.w + v1.w + v2.w + v3.w;
    }
    for (; j < cnt; j++) {
        float4 v = cvt4(A[(size_t)nb[j] * 16 + q]);
        acc.x += v.x; acc.y += v.y; acc.z += v.z; acc.w += v.w;
    }
    float di = g_dis[i];
    acc.x *= di; acc.y *= di; acc.z *= di; acc.w *= di;
    return acc;
}

// gather1: bufBh[i] = fp16(relu(gather + b1))   (GEMM2 input, fp16)
__global__ void k_gather1(const float* __restrict__ b1, int n) {
    int idx = blockIdx.x * blockDim.x + threadIdx.x;
    int i = idx >> 4, q = idx & 15;
    if (i >= n) return;
    float4 acc = gather_node(i, q);
    float4 bb = ((const float4*)b1)[q];
    acc.x = fmaxf(acc.x + bb.x, 0.0f);
    acc.y = fmaxf(acc.y + bb.y, 0.0f);
    acc.z = fmaxf(acc.z + bb.z, 0.0f);
    acc.w = fmaxf(acc.w + bb.w, 0.0f);
    __half2 h0 = __floats2half2_rn(acc.x, acc.y);
    __half2 h1 = __floats2half2_rn(acc.z, acc.w);
    uint2 st; st.x = *(unsigned*)&h0; st.y = *(unsigned*)&h1;
    ((uint2*)(g_bufBh + (size_t)i * 64))[q] = st;
}

// gather2 fused with pooling: pool[batch[i]] += relu(gather + b2)
__global__ void k_gather2_pool(const int* __restrict__ batch,
                               const float* __restrict__ b2, int n) {
    int idx = blockIdx.x * blockDim.x + threadIdx.x;
    int i = idx >> 4, q = idx & 15;
    if (i >= n) return;
    float4 acc = gather_node(i, q);
    float4 bb = ((const float4*)b2)[q];
    acc.x = fmaxf(acc.x + bb.x, 0.0f);
    acc.y = fmaxf(acc.y + bb.y, 0.0f);
    acc.z = fmaxf(acc.z + bb.z, 0.0f);
    acc.w = fmaxf(acc.w + bb.w, 0.0f);
    int g = batch[i];
    red_add_v4(g_pool + g * 64 + q * 4, acc);
}

__global__ void k_final(const float* __restrict__ Wf, const float* __restrict__ bf,
                        float* __restrict__ out) {
    int t = threadIdx.x;
    if (t >= N_GRAPHS * 2) return;
    int g = t >> 1, c = t & 1;
    float acc = 0.0f;
#pragma unroll
    for (int j = 0; j < F_HID; j++)
        acc = fmaf(g_pool[g * 64 + j], Wf[j * 2 + c], acc);
    float cnt = fmaxf(g_cnt[g], 1.0f);
    out[g * 2 + c] = acc / cnt + bf[c];
}

// ---------------------------------------------------------------------------
extern "C" void kernel_launch(void* const* d_in, const int* in_sizes, int n_in,
                              void* d_out, int out_size) {
    const float* x    = (const float*)d_in[0];
    const int*   ei   = (const int*)d_in[1];  // [2, E] int32
    const int*   batch= (const int*)d_in[2];
    const float* W1   = (const float*)d_in[3];
    const float* b1   = (const float*)d_in[4];
    const float* W2   = (const float*)d_in[5];
    const float* b2   = (const float*)d_in[6];
    const float* Wf   = (const float*)d_in[7];
    const float* bf   = (const float*)d_in[8];
    float* out = (float*)d_out;

    int n  = in_sizes[0] / F_IN;   // 100000
    int nE = in_sizes[1] / 2;      // 1600000 (multiple of 4)
    const int* src = ei;
    const int* dst = ei + nE;

    const int T = 256;
    int gN   = (n + T - 1) / T;
    int nE4  = nE / 4;
    int gE4  = (nE4 + T - 1) / T;
    int gN16 = (int)(((size_t)n * 16 + T - 1) / T);
    int gGemm = (n + 127) / 128;

    // graph structure (bucket CSR, single pass) + normalization
    k_zero<<<gN, T>>>(n);
    k_fill<<<gE4, T>>>(src, dst, nE4);
    k_prep<<<gN, T>>>(batch, n);

    // layer 1 (tensor-core GEMM, fp32 X, 4-stage cp.async pipeline)
    k_gemm_mma<F_IN, 16, 4, false><<<gGemm, T>>>(x, W1, n);
    k_gather1<<<gN16, T>>>(b1, n);

    // layer 2 (tensor-core GEMM, fp16 input from gather1, 2-stage)
    k_gemm_mma<F_HID, 32, 2, true><<<gGemm, T>>>(nullptr, W2, n);
    k_gather2_pool<<<gN16, T>>>(batch, b2, n);

    // classifier
    k_final<<<1, T>>>(Wf, bf, out);
}

// round 11
// speedup vs baseline: 1.0848x; 1.0101x over previous
#include <cuda_runtime.h>
#include <cuda_fp16.h>
#include <math.h>

#define NNODES   100000
#define NEDGES   1600000
#define F_IN     128
#define F_HID    64
#define N_GRAPHS 128
#define BUCKET   64   // max in-degree capacity (Poisson(16): P(>=64) ~ 1e-24)

// scratch
__device__ int    g_count[NNODES];                  // in-degree (no self loop)
__device__ int    g_bucket[(size_t)NNODES * BUCKET];// neighbor lists
__device__ float  g_dis[NNODES];                    // (deg+1)^{-1/2}
__device__ __align__(16) __half g_bufAh[(size_t)NNODES * F_HID]; // dis-prescaled feats
__device__ __align__(16) __half g_bufBh[(size_t)NNODES * F_HID]; // layer-1 activations
__device__ float  g_pool[N_GRAPHS * F_HID];
__device__ float  g_cnt[N_GRAPHS];

__device__ __forceinline__ void red_add_v4(float* addr, float4 v) {
    asm volatile("red.global.add.v4.f32 [%0], {%1, %2, %3, %4};"
                 :: "l"(addr), "f"(v.x), "f"(v.y), "f"(v.z), "f"(v.w)
                 : "memory");
}

__device__ __forceinline__ unsigned smem_u32(const void* p) {
    return (unsigned)__cvta_generic_to_shared(p);
}

// ---------------------------------------------------------------------------
__global__ void k_zero(int n) {
    int i = blockIdx.x * blockDim.x + threadIdx.x;
    if (i < n) g_count[i] = 0;
    if (i < N_GRAPHS * F_HID) g_pool[i] = 0.0f;
    if (i < N_GRAPHS) g_cnt[i] = 0.0f;
}

// single-pass bucket fill (histogram + placement in one atomic)
__global__ void k_fill(const int* __restrict__ src,
                       const int* __restrict__ dst, int nE4) {
    int t = blockIdx.x * blockDim.x + threadIdx.x;
    if (t >= nE4) return;
    int4 s4 = ((const int4*)src)[t];
    int4 d4 = ((const int4*)dst)[t];
    int p0 = atomicAdd(&g_count[d4.x], 1);
    int p1 = atomicAdd(&g_count[d4.y], 1);
    int p2 = atomicAdd(&g_count[d4.z], 1);
    int p3 = atomicAdd(&g_count[d4.w], 1);
    if (p0 < BUCKET) g_bucket[(size_t)d4.x * BUCKET + p0] = s4.x;
    if (p1 < BUCKET) g_bucket[(size_t)d4.y * BUCKET + p1] = s4.y;
    if (p2 < BUCKET) g_bucket[(size_t)d4.z * BUCKET + p2] = s4.z;
    if (p3 < BUCKET) g_bucket[(size_t)d4.w * BUCKET + p3] = s4.w;
}

__global__ void k_prep(const int* __restrict__ batch, int n) {
    int i = blockIdx.x * blockDim.x + threadIdx.x;
    if (i >= n) return;
    g_dis[i] = rsqrtf((float)g_count[i] + 1.0f);
    atomicAdd(&g_cnt[batch[i]], 1.0f);
}

// ---------------------------------------------------------------------------
// GEMM1 (fp32 X, K=128): single-stage FULL-TILE cp.async staging.
// Dynamic smem: Ws (64 x 136 halves) + X tile (128 x 132 floats) = ~83KB.
// One big async burst per block maximizes in-flight DRAM bytes.
// ---------------------------------------------------------------------------
__global__ void __launch_bounds__(256) k_gemm1(const float* __restrict__ Xf,
                                               const float* __restrict__ W,
                                               int n) {
    constexpr int K = 128;
    constexpr int WP = K + 8;      // 136 halves
    constexpr int XS = K + 4;      // 132 floats per row (528B, = 4 words mod 32)
    extern __shared__ __align__(16) unsigned char dyn[];
    __half* Ws = (__half*)dyn;                       // 64*136*2 = 17408 B
    float*  Xs = (float*)(dyn + 64 * WP * 2);        // 128*132*4 = 67584 B

    int tid = threadIdx.x;
    int nodeBase = blockIdx.x * 128;

    // kick off the full X tile load first (128 rows x 32 x 16B = 64KB)
#pragma unroll
    for (int o = tid; o < 128 * 32; o += 256) {
        int r = o >> 5, seg = o & 31;
        int node = nodeBase + r;
        unsigned dst = smem_u32(&Xs[r * XS + seg * 4]);
        const void* src = Xf + (size_t)node * K + seg * 4;
        int sz = (node < n) ? 16 : 0;
        asm volatile("cp.async.ca.shared.global [%0], [%1], 16, %2;\n"
                     :: "r"(dst), "l"(src), "r"(sz));
    }
    asm volatile("cp.async.commit_group;\n");

    // W [K][64] fp32 -> Ws[nCol][k] fp16 (overlaps with X tile arrival)
    for (int i = tid; i < K * 64; i += 256) {
        int k = i >> 6, nn = i & 63;
        Ws[nn * WP + k] = __float2half(W[i]);
    }

    asm volatile("cp.async.wait_group 0;\n");
    __syncthreads();

    int warp = tid >> 5, lane = tid & 31;
    int gid = lane >> 2, tg = lane & 3;

    float c[8][4];
#pragma unroll
    for (int i = 0; i < 8; i++)
#pragma unroll
        for (int j = 0; j < 4; j++) c[i][j] = 0.0f;

    const float* xrow = Xs + (warp * 16 + gid) * XS + tg * 2;
#pragma unroll
    for (int kt = 0; kt < 8; kt++) {
        int k0 = kt * 16;
        float2 f0 = *(const float2*)(xrow + k0);
        float2 f1 = *(const float2*)(xrow + k0 + 8 * XS);
        float2 f2 = *(const float2*)(xrow + k0 + 8);
        float2 f3 = *(const float2*)(xrow + k0 + 8 * XS + 8);
        __half2 h0 = __floats2half2_rn(f0.x, f0.y);
        __half2 h1 = __floats2half2_rn(f1.x, f1.y);
        __half2 h2 = __floats2half2_rn(f2.x, f2.y);
        __half2 h3 = __floats2half2_rn(f3.x, f3.y);
        unsigned a0 = *(unsigned*)&h0, a1 = *(unsigned*)&h1;
        unsigned a2 = *(unsigned*)&h2, a3 = *(unsigned*)&h3;
#pragma unroll
        for (int nt = 0; nt < 8; nt++) {
            const __half* br = &Ws[(nt * 8 + gid) * WP + k0 + tg * 2];
            unsigned b0 = *(const unsigned*)br;
            unsigned b1 = *(const unsigned*)(br + 8);
            asm volatile(
                "mma.sync.aligned.m16n8k16.row.col.f32.f16.f16.f32 "
                "{%0,%1,%2,%3}, {%4,%5,%6,%7}, {%8,%9}, {%0,%1,%2,%3};"
                : "+f"(c[nt][0]), "+f"(c[nt][1]),
                  "+f"(c[nt][2]), "+f"(c[nt][3])
                : "r"(a0), "r"(a1), "r"(a2), "r"(a3), "r"(b0), "r"(b1));
        }
    }

    // epilogue: scale by dis, store fp16 (dis-prescaled for gather)
    int node0 = nodeBase + warp * 16 + gid;
    int node1 = node0 + 8;
    if (node0 < n) {
        float d = g_dis[node0];
#pragma unroll
        for (int nt = 0; nt < 8; nt++) {
            __half2 h = __floats2half2_rn(c[nt][0] * d, c[nt][1] * d);
            *(__half2*)&g_bufAh[(size_t)node0 * 64 + nt * 8 + tg * 2] = h;
        }
    }
    if (node1 < n) {
        float d = g_dis[node1];
#pragma unroll
        for (int nt = 0; nt < 8; nt++) {
            __half2 h = __floats2half2_rn(c[nt][2] * d, c[nt][3] * d);
            *(__half2*)&g_bufAh[(size_t)node1 * 64 + nt * 8 + tg * 2] = h;
        }
    }
}

// ---------------------------------------------------------------------------
// GEMM2 (fp16 X from gather1, K=64): 2-stage cp.async pipeline (L2-resident).
// ---------------------------------------------------------------------------
__global__ void __launch_bounds__(256) k_gemm2(const float* __restrict__ W,
                                               int n) {
    constexpr int K = 64;
    constexpr int KC = 32;
    constexpr int WP = K + 8;      // 72 halves
    constexpr int XROWB = 80;      // staged fp16 row stride (bytes)
    __shared__ __half Ws[64 * WP];
    __shared__ __align__(16) unsigned char Xraw[2][128 * XROWB];

    int tid = threadIdx.x;

    for (int i = tid; i < K * 64; i += 256) {
        int k = i >> 6, nn = i & 63;
        Ws[nn * WP + k] = __float2half(W[i]);
    }

    int nodeBase = blockIdx.x * 128;
    int warp = tid >> 5, lane = tid & 31;
    int gid = lane >> 2, tg = lane & 3;

    float c[8][4];
#pragma unroll
    for (int i = 0; i < 8; i++)
#pragma unroll
        for (int j = 0; j < 4; j++) c[i][j] = 0.0f;

    auto stage = [&](int k0, int b) {
#pragma unroll
        for (int o = tid; o < 512; o += 256) {
            int r = o >> 2, seg = o & 3;
            int node = nodeBase + r;
            unsigned dst = smem_u32(&Xraw[b][r * XROWB + seg * 16]);
            const void* src = g_bufBh + (size_t)node * 64 + k0 + seg * 8;
            int sz = (node < n) ? 16 : 0;
            asm volatile("cp.async.ca.shared.global [%0], [%1], 16, %2;\n"
                         :: "r"(dst), "l"(src), "r"(sz));
        }
        asm volatile("cp.async.commit_group;\n");
    };

    stage(0, 0);
    int buf = 0;
    for (int k0 = 0; k0 < K; k0 += KC) {
        asm volatile("cp.async.wait_group 0;\n");
        __syncthreads();
        if (k0 + KC < K) stage(k0 + KC, buf ^ 1);

        const __half* xb = (const __half*)Xraw[buf];
#pragma unroll
        for (int kt = 0; kt < 2; kt++) {
            int kk = kt * 16;
            const __half* p0 = xb + (warp * 16 + gid) * 40 + kk + tg * 2;
            unsigned a0 = *(const unsigned*)p0;
            unsigned a1 = *(const unsigned*)(p0 + 8 * 40);
            unsigned a2 = *(const unsigned*)(p0 + 8);
            unsigned a3 = *(const unsigned*)(p0 + 8 * 40 + 8);
#pragma unroll
            for (int nt = 0; nt < 8; nt++) {
                const __half* br = &Ws[(nt * 8 + gid) * WP + k0 + kk + tg * 2];
                unsigned b0 = *(const unsigned*)br;
                unsigned b1 = *(const unsigned*)(br + 8);
                asm volatile(
                    "mma.sync.aligned.m16n8k16.row.col.f32.f16.f16.f32 "
                    "{%0,%1,%2,%3}, {%4,%5,%6,%7}, {%8,%9}, {%0,%1,%2,%3};"
                    : "+f"(c[nt][0]), "+f"(c[nt][1]),
                      "+f"(c[nt][2]), "+f"(c[nt][3])
                    : "r"(a0), "r"(a1), "r"(a2), "r"(a3), "r"(b0), "r"(b1));
            }
        }
        buf ^= 1;
        __syncthreads();
    }

    int node0 = nodeBase + warp * 16 + gid;
    int node1 = node0 + 8;
    if (node0 < n) {
        float d = g_dis[node0];
#pragma unroll
        for (int nt = 0; nt < 8; nt++) {
            __half2 h = __floats2half2_rn(c[nt][0] * d, c[nt][1] * d);
            *(__half2*)&g_bufAh[(size_t)node0 * 64 + nt * 8 + tg * 2] = h;
        }
    }
    if (node1 < n) {
        float d = g_dis[node1];
#pragma unroll
        for (int nt = 0; nt < 8; nt++) {
            __half2 h = __floats2half2_rn(c[nt][2] * d, c[nt][3] * d);
            *(__half2*)&g_bufAh[(size_t)node1 * 64 + nt * 8 + tg * 2] = h;
        }
    }
}

// ---------------------------------------------------------------------------
// gather core on dis-prescaled fp16 features (16 lanes/node x 8B):
//   out_i = dis_i * ( scaled[i] + sum_s scaled[s] )
// ---------------------------------------------------------------------------
__device__ __forceinline__ float4 cvt4(uint2 u) {
    float2 lo = __half22float2(*(__half2*)&u.x);
    float2 hi = __half22float2(*(__half2*)&u.y);
    return make_float4(lo.x, lo.y, hi.x, hi.y);
}

__device__ __forceinline__ float4 gather_node(int i, int q) {
    const uint2* A = (const uint2*)g_bufAh;   // row = 16 x 8B
    float4 acc = cvt4(A[(size_t)i * 16 + q]); // self term (already dis_i-scaled)
    int cnt = min(g_count[i], BUCKET);
    const int* nb = g_bucket + (size_t)i * BUCKET;
    int j = 0;
    for (; j + 4 <= cnt; j += 4) {
        int s0 = nb[j], s1 = nb[j + 1], s2 = nb[j + 2], s3 = nb[j + 3];
        uint2 u0 = A[(size_t)s0 * 16 + q];
        uint2 u1 = A[(size_t)s1 * 16 + q];
        uint2 u2 = A[(size_t)s2 * 16 + q];
        uint2 u3 = A[(size_t)s3 * 16 + q];
        float4 v0 = cvt4(u0), v1 = cvt4(u1), v2 = cvt4(u2), v3 = cvt4(u3);
        acc.x += v0.x + v1.x + v2.x + v3.x;
        acc.y += v0.y + v1.y + v2.y + v3.y;
        acc.z += v0.z + v1.z + v2.z + v3.z;
        acc.w += v0.w + v1.w + v2.w + v3.w;
    }
    for (; j < cnt; j++) {
        float4 v = cvt4(A[(size_t)nb[j] * 16 + q]);
        acc.x += v.x; acc.y += v.y; acc.z += v.z; acc.w += v.w;
    }
    float di = g_dis[i];
    acc.x *= di; acc.y *= di; acc.z *= di; acc.w *= di;
    return acc;
}

// gather1: bufBh[i] = fp16(relu(gather + b1))   (GEMM2 input, fp16)
__global__ void k_gather1(const float* __restrict__ b1, int n) {
    int idx = blockIdx.x * blockDim.x + threadIdx.x;
    int i = idx >> 4, q = idx & 15;
    if (i >= n) return;
    float4 acc = gather_node(i, q);
    float4 bb = ((const float4*)b1)[q];
    acc.x = fmaxf(acc.x + bb.x, 0.0f);
    acc.y = fmaxf(acc.y + bb.y, 0.0f);
    acc.z = fmaxf(acc.z + bb.z, 0.0f);
    acc.w = fmaxf(acc.w + bb.w, 0.0f);
    __half2 h0 = __floats2half2_rn(acc.x, acc.y);
    __half2 h1 = __floats2half2_rn(acc.z, acc.w);
    uint2 st; st.x = *(unsigned*)&h0; st.y = *(unsigned*)&h1;
    ((uint2*)(g_bufBh + (size_t)i * 64))[q] = st;
}

// gather2 fused with pooling: pool[batch[i]] += relu(gather + b2)
__global__ void k_gather2_pool(const int* __restrict__ batch,
                               const float* __restrict__ b2, int n) {
    int idx = blockIdx.x * blockDim.x + threadIdx.x;
    int i = idx >> 4, q = idx & 15;
    if (i >= n) return;
    float4 acc = gather_node(i, q);
    float4 bb = ((const float4*)b2)[q];
    acc.x = fmaxf(acc.x + bb.x, 0.0f);
    acc.y = fmaxf(acc.y + bb.y, 0.0f);
    acc.z = fmaxf(acc.z + bb.z, 0.0f);
    acc.w = fmaxf(acc.w + bb.w, 0.0f);
    int g = batch[i];
    red_add_v4(g_pool + g * 64 + q * 4, acc);
}

__global__ void k_final(const float* __restrict__ Wf, const float* __restrict__ bf,
                        float* __restrict__ out) {
    int t = threadIdx.x;
    if (t >= N_GRAPHS * 2) return;
    int g = t >> 1, c = t & 1;
    float acc = 0.0f;
#pragma unroll
    for (int j = 0; j < F_HID; j++)
        acc = fmaf(g_pool[g * 64 + j], Wf[j * 2 + c], acc);
    float cnt = fmaxf(g_cnt[g], 1.0f);
    out[g * 2 + c] = acc / cnt + bf[c];
}

// ---------------------------------------------------------------------------
extern "C" void kernel_launch(void* const* d_in, const int* in_sizes, int n_in,
                              void* d_out, int out_size) {
    const float* x    = (const float*)d_in[0];
    const int*   ei   = (const int*)d_in[1];  // [2, E] int32
    const int*   batch= (const int*)d_in[2];
    const float* W1   = (const float*)d_in[3];
    const float* b1   = (const float*)d_in[4];
    const float* W2   = (const float*)d_in[5];
    const float* b2   = (const float*)d_in[6];
    const float* Wf   = (const float*)d_in[7];
    const float* bf   = (const float*)d_in[8];
    float* out = (float*)d_out;

    int n  = in_sizes[0] / F_IN;   // 100000
    int nE = in_sizes[1] / 2;      // 1600000 (multiple of 4)
    const int* src = ei;
    const int* dst = ei + nE;

    const int T = 256;
    int gN   = (n + T - 1) / T;
    int nE4  = nE / 4;
    int gE4  = (nE4 + T - 1) / T;
    int gN16 = (int)(((size_t)n * 16 + T - 1) / T);
    int gGemm = (n + 127) / 128;

    // GEMM1 dynamic smem: Ws 17408B + X tile 67584B
    const int dynSmem = 64 * 136 * 2 + 128 * 132 * 4;
    cudaFuncSetAttribute(k_gemm1, cudaFuncAttributeMaxDynamicSharedMemorySize,
                         dynSmem);

    // graph structure (bucket CSR, single pass) + normalization
    k_zero<<<gN, T>>>(n);
    k_fill<<<gE4, T>>>(src, dst, nE4);
    k_prep<<<gN, T>>>(batch, n);

    // layer 1 (full-tile cp.async staging, fp32 X)
    k_gemm1<<<gGemm, T, dynSmem>>>(x, W1, n);
    k_gather1<<<gN16, T>>>(b1, n);

    // layer 2 (fp16 input from gather1, 2-stage pipeline)
    k_gemm2<<<gGemm, T>>>(W2, n);
    k_gather2_pool<<<gN16, T>>>(batch, b2, n);

    // classifier
    k_final<<<1, T>>>(Wf, bf, out);
}

// round 12
// speedup vs baseline: 1.0989x; 1.0130x over previous
#include <cuda_runtime.h>
#include <cuda_fp16.h>
#include <math.h>

#define NNODES   100000
#define NEDGES   1600000
#define F_IN     128
#define F_HID    64
#define N_GRAPHS 128
#define BUCKET   64   // max in-degree capacity (Poisson(16): P(>=64) ~ 1e-24)

// scratch
__device__ int    g_count[NNODES];                  // in-degree (no self loop)
__device__ int    g_bucket[(size_t)NNODES * BUCKET];// neighbor lists
__device__ float  g_dis[NNODES];                    // (deg+1)^{-1/2}
__device__ __align__(16) __half g_bufAh[(size_t)NNODES * F_HID]; // dis-prescaled feats
__device__ __align__(16) __half g_bufBh[(size_t)NNODES * F_HID]; // layer-1 activations
__device__ float  g_pool[N_GRAPHS * F_HID];
__device__ float  g_cnt[N_GRAPHS];

__device__ __forceinline__ void red_add_v4(float* addr, float4 v) {
    asm volatile("red.global.add.v4.f32 [%0], {%1, %2, %3, %4};"
                 :: "l"(addr), "f"(v.x), "f"(v.y), "f"(v.z), "f"(v.w)
                 : "memory");
}

// ---------------------------------------------------------------------------
__global__ void k_zero(int n) {
    int i = blockIdx.x * blockDim.x + threadIdx.x;
    if (i < n) g_count[i] = 0;
    if (i < N_GRAPHS * F_HID) g_pool[i] = 0.0f;
    if (i < N_GRAPHS) g_cnt[i] = 0.0f;
}

// single-pass bucket fill (histogram + placement in one atomic)
__global__ void k_fill(const int* __restrict__ src,
                       const int* __restrict__ dst, int nE4) {
    int t = blockIdx.x * blockDim.x + threadIdx.x;
    if (t >= nE4) return;
    int4 s4 = ((const int4*)src)[t];
    int4 d4 = ((const int4*)dst)[t];
    int p0 = atomicAdd(&g_count[d4.x], 1);
    int p1 = atomicAdd(&g_count[d4.y], 1);
    int p2 = atomicAdd(&g_count[d4.z], 1);
    int p3 = atomicAdd(&g_count[d4.w], 1);
    if (p0 < BUCKET) g_bucket[(size_t)d4.x * BUCKET + p0] = s4.x;
    if (p1 < BUCKET) g_bucket[(size_t)d4.y * BUCKET + p1] = s4.y;
    if (p2 < BUCKET) g_bucket[(size_t)d4.z * BUCKET + p2] = s4.z;
    if (p3 < BUCKET) g_bucket[(size_t)d4.w * BUCKET + p3] = s4.w;
}

__global__ void k_prep(const int* __restrict__ batch, int n) {
    int i = blockIdx.x * blockDim.x + threadIdx.x;
    if (i >= n) return;
    g_dis[i] = rsqrtf((float)g_count[i] + 1.0f);
    atomicAdd(&g_cnt[batch[i]], 1.0f);
}

// ---------------------------------------------------------------------------
// GEMM1 (fp32 X, K=128): A-fragments loaded DIRECTLY from global (LDG.64),
// all 32 per-thread loads front-batched for max DRAM MLP. No X smem, no
// inner syncthreads. W held transposed fp16 in smem (conflict-free LDS).
// Warp w: nodes w*16..w*16+15, all 64 cols. OOB rows clamped (not stored).
// ---------------------------------------------------------------------------
__global__ void __launch_bounds__(256) k_gemm1(const float* __restrict__ Xf,
                                               const float* __restrict__ W,
                                               int n) {
    constexpr int K = 128;
    constexpr int WP = K + 8;      // 136 halves; row -> bank-group 4*nCol mod 32
    __shared__ __half Ws[64 * WP];

    int tid = threadIdx.x;
    for (int i = tid; i < K * 64; i += 256) {
        int k = i >> 6, nn = i & 63;
        Ws[nn * WP + k] = __float2half(W[i]);
    }
    __syncthreads();

    int nodeBase = blockIdx.x * 128;
    int warp = tid >> 5, lane = tid & 31;
    int gid = lane >> 2, tg = lane & 3;
    int r0 = nodeBase + warp * 16 + gid;
    int r1 = r0 + 8;
    // clamp OOB rows: fragment rows map 1:1 to output rows, garbage never
    // crosses rows in D = A@B; clamped rows are simply not stored.
    const float* x0 = Xf + (size_t)min(r0, n - 1) * K + tg * 2;
    const float* x1 = Xf + (size_t)min(r1, n - 1) * K + tg * 2;

    // front-batch all 32 fragment loads (8 kt x 4 frags of 8B)
    float2 f0[8], f1[8], f2[8], f3[8];
#pragma unroll
    for (int kt = 0; kt < 8; kt++) {
        f0[kt] = *(const float2*)(x0 + kt * 16);
        f1[kt] = *(const float2*)(x1 + kt * 16);
        f2[kt] = *(const float2*)(x0 + kt * 16 + 8);
        f3[kt] = *(const float2*)(x1 + kt * 16 + 8);
    }

    float c[8][4];
#pragma unroll
    for (int i = 0; i < 8; i++)
#pragma unroll
        for (int j = 0; j < 4; j++) c[i][j] = 0.0f;

#pragma unroll
    for (int kt = 0; kt < 8; kt++) {
        int k0 = kt * 16;
        __half2 h0 = __floats2half2_rn(f0[kt].x, f0[kt].y);
        __half2 h1 = __floats2half2_rn(f1[kt].x, f1[kt].y);
        __half2 h2 = __floats2half2_rn(f2[kt].x, f2[kt].y);
        __half2 h3 = __floats2half2_rn(f3[kt].x, f3[kt].y);
        unsigned a0 = *(unsigned*)&h0, a1 = *(unsigned*)&h1;
        unsigned a2 = *(unsigned*)&h2, a3 = *(unsigned*)&h3;
#pragma unroll
        for (int nt = 0; nt < 8; nt++) {
            const __half* br = &Ws[(nt * 8 + gid) * WP + k0 + tg * 2];
            unsigned b0 = *(const unsigned*)br;
            unsigned b1 = *(const unsigned*)(br + 8);
            asm volatile(
                "mma.sync.aligned.m16n8k16.row.col.f32.f16.f16.f32 "
                "{%0,%1,%2,%3}, {%4,%5,%6,%7}, {%8,%9}, {%0,%1,%2,%3};"
                : "+f"(c[nt][0]), "+f"(c[nt][1]),
                  "+f"(c[nt][2]), "+f"(c[nt][3])
                : "r"(a0), "r"(a1), "r"(a2), "r"(a3), "r"(b0), "r"(b1));
        }
    }

    // epilogue: scale by dis, store fp16 (dis-prescaled for gather)
    if (r0 < n) {
        float d = g_dis[r0];
#pragma unroll
        for (int nt = 0; nt < 8; nt++) {
            __half2 h = __floats2half2_rn(c[nt][0] * d, c[nt][1] * d);
            *(__half2*)&g_bufAh[(size_t)r0 * 64 + nt * 8 + tg * 2] = h;
        }
    }
    if (r1 < n) {
        float d = g_dis[r1];
#pragma unroll
        for (int nt = 0; nt < 8; nt++) {
            __half2 h = __floats2half2_rn(c[nt][2] * d, c[nt][3] * d);
            *(__half2*)&g_bufAh[(size_t)r1 * 64 + nt * 8 + tg * 2] = h;
        }
    }
}

// ---------------------------------------------------------------------------
// GEMM2 (fp16 X from gather1, K=64): same direct-LDG scheme (L2-resident).
// ---------------------------------------------------------------------------
__global__ void __launch_bounds__(256) k_gemm2(const float* __restrict__ W,
                                               int n) {
    constexpr int K = 64;
    constexpr int WP = K + 8;      // 72 halves
    __shared__ __half Ws[64 * WP];

    int tid = threadIdx.x;
    for (int i = tid; i < K * 64; i += 256) {
        int k = i >> 6, nn = i & 63;
        Ws[nn * WP + k] = __float2half(W[i]);
    }
    __syncthreads();

    int nodeBase = blockIdx.x * 128;
    int warp = tid >> 5, lane = tid & 31;
    int gid = lane >> 2, tg = lane & 3;
    int r0 = nodeBase + warp * 16 + gid;
    int r1 = r0 + 8;
    const __half* x0 = g_bufBh + (size_t)min(r0, n - 1) * K + tg * 2;
    const __half* x1 = g_bufBh + (size_t)min(r1, n - 1) * K + tg * 2;

    // front-batch all 16 fragment loads (4 kt x 4 frags of 4B)
    unsigned a0[4], a1[4], a2[4], a3[4];
#pragma unroll
    for (int kt = 0; kt < 4; kt++) {
        a0[kt] = *(const unsigned*)(x0 + kt * 16);
        a1[kt] = *(const unsigned*)(x1 + kt * 16);
        a2[kt] = *(const unsigned*)(x0 + kt * 16 + 8);
        a3[kt] = *(const unsigned*)(x1 + kt * 16 + 8);
    }

    float c[8][4];
#pragma unroll
    for (int i = 0; i < 8; i++)
#pragma unroll
        for (int j = 0; j < 4; j++) c[i][j] = 0.0f;

#pragma unroll
    for (int kt = 0; kt < 4; kt++) {
        int k0 = kt * 16;
#pragma unroll
        for (int nt = 0; nt < 8; nt++) {
            const __half* br = &Ws[(nt * 8 + gid) * WP + k0 + tg * 2];
            unsigned b0 = *(const unsigned*)br;
            unsigned b1 = *(const unsigned*)(br + 8);
            asm volatile(
                "mma.sync.aligned.m16n8k16.row.col.f32.f16.f16.f32 "
                "{%0,%1,%2,%3}, {%4,%5,%6,%7}, {%8,%9}, {%0,%1,%2,%3};"
                : "+f"(c[nt][0]), "+f"(c[nt][1]),
                  "+f"(c[nt][2]), "+f"(c[nt][3])
                : "r"(a0[kt]), "r"(a1[kt]), "r"(a2[kt]), "r"(a3[kt]),
                  "r"(b0), "r"(b1));
        }
    }

    if (r0 < n) {
        float d = g_dis[r0];
#pragma unroll
        for (int nt = 0; nt < 8; nt++) {
            __half2 h = __floats2half2_rn(c[nt][0] * d, c[nt][1] * d);
            *(__half2*)&g_bufAh[(size_t)r0 * 64 + nt * 8 + tg * 2] = h;
        }
    }
    if (r1 < n) {
        float d = g_dis[r1];
#pragma unroll
        for (int nt = 0; nt < 8; nt++) {
            __half2 h = __floats2half2_rn(c[nt][2] * d, c[nt][3] * d);
            *(__half2*)&g_bufAh[(size_t)r1 * 64 + nt * 8 + tg * 2] = h;
        }
    }
}

// ---------------------------------------------------------------------------
// gather core on dis-prescaled fp16 features (16 lanes/node x 8B):
//   out_i = dis_i * ( scaled[i] + sum_s scaled[s] )
// ---------------------------------------------------------------------------
__device__ __forceinline__ float4 cvt4(uint2 u) {
    float2 lo = __half22float2(*(__half2*)&u.x);
    float2 hi = __half22float2(*(__half2*)&u.y);
    return make_float4(lo.x, lo.y, hi.x, hi.y);
}

__device__ __forceinline__ float4 gather_node(int i, int q) {
    const uint2* A = (const uint2*)g_bufAh;   // row = 16 x 8B
    float4 acc = cvt4(A[(size_t)i * 16 + q]); // self term (already dis_i-scaled)
    int cnt = min(g_count[i], BUCKET);
    const int* nb = g_bucket + (size_t)i * BUCKET;
    int j = 0;
    for (; j + 4 <= cnt; j += 4) {
        int s0 = nb[j], s1 = nb[j + 1], s2 = nb[j + 2], s3 = nb[j + 3];
        uint2 u0 = A[(size_t)s0 * 16 + q];
        uint2 u1 = A[(size_t)s1 * 16 + q];
        uint2 u2 = A[(size_t)s2 * 16 + q];
        uint2 u3 = A[(size_t)s3 * 16 + q];
        float4 v0 = cvt4(u0), v1 = cvt4(u1), v2 = cvt4(u2), v3 = cvt4(u3);
        acc.x += v0.x + v1.x + v2.x + v3.x;
        acc.y += v0.y + v1.y + v2.y + v3.y;
        acc.z += v0.z + v1.z + v2.z + v3.z;
        acc.w += v0.w + v1.w + v2.w + v3.w;
    }
    for (; j < cnt; j++) {
        float4 v = cvt4(A[(size_t)nb[j] * 16 + q]);
        acc.x += v.x; acc.y += v.y; acc.z += v.z; acc.w += v.w;
    }
    float di = g_dis[i];
    acc.x *= di; acc.y *= di; acc.z *= di; acc.w *= di;
    return acc;
}

// gather1: bufBh[i] = fp16(relu(gather + b1))   (GEMM2 input, fp16)
__global__ void k_gather1(const float* __restrict__ b1, int n) {
    int idx = blockIdx.x * blockDim.x + threadIdx.x;
    int i = idx >> 4, q = idx & 15;
    if (i >= n) return;
    float4 acc = gather_node(i, q);
    float4 bb = ((const float4*)b1)[q];
    acc.x = fmaxf(acc.x + bb.x, 0.0f);
    acc.y = fmaxf(acc.y + bb.y, 0.0f);
    acc.z = fmaxf(acc.z + bb.z, 0.0f);
    acc.w = fmaxf(acc.w + bb.w, 0.0f);
    __half2 h0 = __floats2half2_rn(acc.x, acc.y);
    __half2 h1 = __floats2half2_rn(acc.z, acc.w);
    uint2 st; st.x = *(unsigned*)&h0; st.y = *(unsigned*)&h1;
    ((uint2*)(g_bufBh + (size_t)i * 64))[q] = st;
}

// gather2 fused with pooling: pool[batch[i]] += relu(gather + b2)
__global__ void k_gather2_pool(const int* __restrict__ batch,
                               const float* __restrict__ b2, int n) {
    int idx = blockIdx.x * blockDim.x + threadIdx.x;
    int i = idx >> 4, q = idx & 15;
    if (i >= n) return;
    float4 acc = gather_node(i, q);
    float4 bb = ((const float4*)b2)[q];
    acc.x = fmaxf(acc.x + bb.x, 0.0f);
    acc.y = fmaxf(acc.y + bb.y, 0.0f);
    acc.z = fmaxf(acc.z + bb.z, 0.0f);
    acc.w = fmaxf(acc.w + bb.w, 0.0f);
    int g = batch[i];
    red_add_v4(g_pool + g * 64 + q * 4, acc);
}

__global__ void k_final(const float* __restrict__ Wf, const float* __restrict__ bf,
                        float* __restrict__ out) {
    int t = threadIdx.x;
    if (t >= N_GRAPHS * 2) return;
    int g = t >> 1, c = t & 1;
    float acc = 0.0f;
#pragma unroll
    for (int j = 0; j < F_HID; j++)
        acc = fmaf(g_pool[g * 64 + j], Wf[j * 2 + c], acc);
    float cnt = fmaxf(g_cnt[g], 1.0f);
    out[g * 2 + c] = acc / cnt + bf[c];
}

// ---------------------------------------------------------------------------
extern "C" void kernel_launch(void* const* d_in, const int* in_sizes, int n_in,
                              void* d_out, int out_size) {
    const float* x    = (const float*)d_in[0];
    const int*   ei   = (const int*)d_in[1];  // [2, E] int32
    const int*   batch= (const int*)d_in[2];
    const float* W1   = (const float*)d_in[3];
    const float* b1   = (const float*)d_in[4];
    const float* W2   = (const float*)d_in[5];
    const float* b2   = (const float*)d_in[6];
    const float* Wf   = (const float*)d_in[7];
    const float* bf   = (const float*)d_in[8];
    float* out = (float*)d_out;

    int n  = in_sizes[0] / F_IN;   // 100000
    int nE = in_sizes[1] / 2;      // 1600000 (multiple of 4)
    const int* src = ei;
    const int* dst = ei + nE;

    const int T = 256;
    int gN   = (n + T - 1) / T;
    int nE4  = nE / 4;
    int gE4  = (nE4 + T - 1) / T;
    int gN16 = (int)(((size_t)n * 16 + T - 1) / T);
    int gGemm = (n + 127) / 128;

    // graph structure (bucket CSR, single pass) + normalization
    k_zero<<<gN, T>>>(n);
    k_fill<<<gE4, T>>>(src, dst, nE4);
    k_prep<<<gN, T>>>(batch, n);

    // layer 1 (direct-LDG fragment GEMM, fp32 X)
    k_gemm1<<<gGemm, T>>>(x, W1, n);
    k_gather1<<<gN16, T>>>(b1, n);

    // layer 2 (direct-LDG fragment GEMM, fp16 input)
    k_gemm2<<<gGemm, T>>>(W2, n);
    k_gather2_pool<<<gN16, T>>>(batch, b2, n);

    // classifier
    k_final<<<1, T>>>(Wf, bf, out);
}